// round 4
// baseline (speedup 1.0000x reference)
#include <cuda_runtime.h>
#include <cstdint>
#include <cstddef>

#define N_NODES  100000
#define N_EDGES  3200000
#define FEAT     128
#define NUM_RELS 16
#define NUM_BASES 8

// Scratch (static device globals — no runtime allocation allowed).
__device__ float g_h [(size_t)NUM_RELS * N_NODES * FEAT];  // 819 MB: h[r][n][o]
__device__ uint32_t g_wt[(size_t)NUM_RELS * FEAT * FEAT];  // 1 MB: Wt[r][o][k], tf32 bits
__device__ int   g_idx64;

// ---------------------------------------------------------------------------
// Helpers
// ---------------------------------------------------------------------------
__device__ __forceinline__ uint32_t f2tf32(float f) {
    uint32_t r;
    asm("cvt.rna.tf32.f32 %0, %1;" : "=r"(r) : "f"(f));
    return r;
}

__device__ __forceinline__ void mma_tf32(float* c,
                                         uint32_t a0, uint32_t a1, uint32_t a2, uint32_t a3,
                                         uint32_t b0, uint32_t b1) {
    asm volatile("mma.sync.aligned.m16n8k8.row.col.f32.tf32.tf32.f32 "
                 "{%0,%1,%2,%3}, {%4,%5,%6,%7}, {%8,%9}, {%0,%1,%2,%3};"
                 : "+f"(c[0]), "+f"(c[1]), "+f"(c[2]), "+f"(c[3])
                 : "r"(a0), "r"(a1), "r"(a2), "r"(a3), "r"(b0), "r"(b1));
}

// ---------------------------------------------------------------------------
// Probe: int64 vs int32 indices
// ---------------------------------------------------------------------------
__global__ void probe_kernel(const void* src) {
    if (blockIdx.x == 0 && threadIdx.x == 0) {
        const long long* p = (const long long*)src;
        int is64 = 1;
        for (int i = 0; i < 1024; i++) {
            long long v = p[i];
            if (v < 0 || v >= (long long)N_NODES) { is64 = 0; break; }
        }
        g_idx64 = is64;
    }
}

// ---------------------------------------------------------------------------
// Wt[r][o][k] = sum_b w_comp[r][b] * weight[b][k][o], stored as tf32 bits.
// ---------------------------------------------------------------------------
__global__ __launch_bounds__(256) void wgen_kernel(const float* __restrict__ weight,
                                                   const float* __restrict__ w_comp) {
    int idx = blockIdx.x * 256 + threadIdx.x;            // 16*128*128 = 262144
    if (idx >= NUM_RELS * FEAT * FEAT) return;
    int r = idx >> 14;
    int rem = idx & 16383;
    int o = rem >> 7;
    int k = rem & 127;
    float acc = 0.f;
#pragma unroll
    for (int b = 0; b < NUM_BASES; b++)
        acc += w_comp[r * NUM_BASES + b] * weight[((size_t)b * FEAT + k) * FEAT + o];
    g_wt[idx] = f2tf32(acc);
}

// ---------------------------------------------------------------------------
// h_gemm: per 128-row M-tile, x tile resident in SMEM (tf32), loop 16 rels:
//   h[r][m0:m0+128][:] = x_tile @ Wt[r]^T   via mma.sync m16n8k8 tf32.
// 256 threads = 8 warps as 4(M) x 2(N); warp tile 32x64; K=128 (16 k-steps).
// SMEM: As[128][132] + Bs[128][132] uint32 (tf32 bits), pad 132 for
// conflict-free fragment loads.
// ---------------------------------------------------------------------------
#define PITCH 132
static constexpr int SMEM_TILE_WORDS = 128 * PITCH;                 // 16896
static constexpr size_t SMEM_TOT = 2u * SMEM_TILE_WORDS * 4u;       // 135168 B

__global__ __launch_bounds__(256) void h_gemm(const float* __restrict__ x) {
    extern __shared__ uint32_t smem[];
    uint32_t* As = smem;
    uint32_t* Bs = smem + SMEM_TILE_WORDS;

    const int tid    = threadIdx.x;
    const int wid    = tid >> 5;
    const int lane   = tid & 31;
    const int warp_m = wid & 3;      // 0..3 -> M groups of 32
    const int warp_n = wid >> 2;     // 0..1 -> N groups of 64
    const int m0     = blockIdx.x * 128;
    const int grp    = lane >> 2;    // 0..7
    const int tig    = lane & 3;     // 0..3

    // ---- Load A tile (x rows m0..m0+127) as tf32, zero-fill OOB ----
    for (int u = tid; u < 128 * 32; u += 256) {         // unit = 4 floats
        int row = u >> 5, c4 = (u & 31) * 4;
        float4 v = make_float4(0.f, 0.f, 0.f, 0.f);
        if (m0 + row < N_NODES)
            v = *(const float4*)(x + (size_t)(m0 + row) * FEAT + c4);
        uint32_t* dst = As + row * PITCH + c4;
        dst[0] = f2tf32(v.x); dst[1] = f2tf32(v.y);
        dst[2] = f2tf32(v.z); dst[3] = f2tf32(v.w);
    }

    for (int r = 0; r < NUM_RELS; r++) {
        __syncthreads();   // prev k-loop's Bs reads done (and A ready on r=0)

        // ---- Load B tile = Wt[r][o][k] (already tf32 bits) ----
        const uint32_t* wt = g_wt + (size_t)r * FEAT * FEAT;
        for (int u = tid; u < 128 * 32; u += 256) {
            int row = u >> 5, c4 = (u & 31) * 4;
            *(uint4*)(Bs + row * PITCH + c4) = *(const uint4*)(wt + row * FEAT + c4);
        }
        __syncthreads();

        // ---- Accumulate ----
        float acc[2][8][4];
#pragma unroll
        for (int i = 0; i < 2; i++)
#pragma unroll
            for (int j = 0; j < 8; j++)
#pragma unroll
                for (int q = 0; q < 4; q++) acc[i][j][q] = 0.f;

#pragma unroll
        for (int ks = 0; ks < 16; ks++) {
            const int k0 = ks * 8;
            uint32_t bfr[8][2];
#pragma unroll
            for (int j = 0; j < 8; j++) {
                const uint32_t* bp = Bs + (warp_n * 64 + j * 8 + grp) * PITCH + k0 + tig;
                bfr[j][0] = bp[0];
                bfr[j][1] = bp[4];
            }
#pragma unroll
            for (int i = 0; i < 2; i++) {
                const uint32_t* ap = As + (warp_m * 32 + i * 16 + grp) * PITCH + k0 + tig;
                uint32_t a0 = ap[0];
                uint32_t a1 = ap[8 * PITCH];
                uint32_t a2 = ap[4];
                uint32_t a3 = ap[8 * PITCH + 4];
#pragma unroll
                for (int j = 0; j < 8; j++)
                    mma_tf32(acc[i][j], a0, a1, a2, a3, bfr[j][0], bfr[j][1]);
            }
        }

        // ---- Epilogue: regs -> g_h[r] ----
        float* hr = g_h + (size_t)r * N_NODES * FEAT;
#pragma unroll
        for (int i = 0; i < 2; i++) {
            int row_lo = m0 + warp_m * 32 + i * 16 + grp;
            int row_hi = row_lo + 8;
#pragma unroll
            for (int j = 0; j < 8; j++) {
                int col = warp_n * 64 + j * 8 + 2 * tig;
                if (row_lo < N_NODES)
                    *(float2*)(hr + (size_t)row_lo * FEAT + col) =
                        make_float2(acc[i][j][0], acc[i][j][1]);
                if (row_hi < N_NODES)
                    *(float2*)(hr + (size_t)row_hi * FEAT + col) =
                        make_float2(acc[i][j][2], acc[i][j][3]);
            }
        }
    }
}

// ---------------------------------------------------------------------------
// out[n][o] = h_bias[o]
// ---------------------------------------------------------------------------
__global__ __launch_bounds__(256) void init_out(float4* __restrict__ out,
                                                const float4* __restrict__ bias) {
    size_t t = (size_t)blockIdx.x * blockDim.x + threadIdx.x;
    const size_t total = (size_t)N_NODES * (FEAT / 4);
    if (t < total) out[t] = bias[t & 31];
}

// ---------------------------------------------------------------------------
// Edge scatter: gather h[etype][src], red.add.v4 into out[dst].
// ---------------------------------------------------------------------------
#define EDGES_PER_WARP 4
__global__ __launch_bounds__(256) void edge_kernel(const void* __restrict__ srcp,
                                                   const void* __restrict__ dstp,
                                                   const void* __restrict__ etp,
                                                   float* __restrict__ out) {
    const int warp = threadIdx.x >> 5;
    const int lane = threadIdx.x & 31;
    const int e0 = (blockIdx.x * 8 + warp) * EDGES_PER_WARP;
    if (e0 >= N_EDGES) return;
    const int idx64 = g_idx64;

    float4 v[EDGES_PER_WARP];
    float4* op[EDGES_PER_WARP];
    int valid[EDGES_PER_WARP];

#pragma unroll
    for (int q = 0; q < EDGES_PER_WARP; q++) {
        int e = e0 + q;
        valid[q] = (e < N_EDGES);
        if (valid[q]) {
            long long s, d, r;
            if (idx64) {
                s = ((const long long*)srcp)[e];
                d = ((const long long*)dstp)[e];
                r = ((const long long*)etp)[e];
            } else {
                s = ((const int*)srcp)[e];
                d = ((const int*)dstp)[e];
                r = ((const int*)etp)[e];
            }
            const float4* hp = (const float4*)g_h +
                               ((size_t)r * N_NODES + (size_t)s) * (FEAT / 4);
            v[q]  = hp[lane];
            op[q] = (float4*)out + (size_t)d * (FEAT / 4) + lane;
        }
    }

#pragma unroll
    for (int q = 0; q < EDGES_PER_WARP; q++) {
        if (valid[q]) {
            asm volatile("red.global.add.v4.f32 [%0], {%1, %2, %3, %4};"
                         :: "l"(op[q]), "f"(v[q].x), "f"(v[q].y),
                            "f"(v[q].z), "f"(v[q].w)
                         : "memory");
        }
    }
}

// ---------------------------------------------------------------------------
// Launch
// ---------------------------------------------------------------------------
extern "C" void kernel_launch(void* const* d_in, const int* in_sizes, int n_in,
                              void* d_out, int out_size) {
    const float* x      = (const float*)d_in[0];
    const float* weight = (const float*)d_in[1];
    const float* w_comp = (const float*)d_in[2];
    const float* h_bias = (const float*)d_in[3];
    const void*  src    = d_in[4];
    const void*  dst    = d_in[5];
    const void*  etyp   = d_in[6];
    float*       out    = (float*)d_out;

    cudaFuncSetAttribute(h_gemm, cudaFuncAttributeMaxDynamicSharedMemorySize,
                         (int)SMEM_TOT);

    probe_kernel<<<1, 1>>>(src);
    wgen_kernel<<<(NUM_RELS * FEAT * FEAT + 255) / 256, 256>>>(weight, w_comp);

    h_gemm<<<(N_NODES + 127) / 128, 256, SMEM_TOT>>>(x);

    const int total4 = N_NODES * (FEAT / 4);
    init_out<<<(total4 + 255) / 256, 256>>>((float4*)out, (const float4*)h_bias);

    const int warps_needed = (N_EDGES + EDGES_PER_WARP - 1) / EDGES_PER_WARP;
    edge_kernel<<<(warps_needed + 7) / 8, 256>>>(src, dst, etyp, out);
}

// round 5
// speedup vs baseline: 1.2782x; 1.2782x over previous
#include <cuda_runtime.h>
#include <cstdint>
#include <cstddef>

#define N_NODES  100000
#define N_EDGES  3200000
#define FEAT     128
#define NUM_RELS 16
#define NUM_BASES 8
#define KTOT     (NUM_BASES * FEAT)   // 1024

#define NBLK_SCAN 196                 // 196 * 512 = 100352 >= N_NODES

// Scratch (static device globals — no runtime allocation allowed).
__device__ float g_agg[(size_t)N_NODES * NUM_BASES * FEAT];  // 410 MB: agg[d][b][k]
__device__ int   g_deg [N_NODES];
__device__ int   g_off [N_NODES];
__device__ int   g_cur [N_NODES];
__device__ int   g_pack[N_EDGES];                            // (et<<17)|src
__device__ int   g_part [NBLK_SCAN];
__device__ int   g_partx[NBLK_SCAN];
__device__ int   g_idx64;

// ---------------------------------------------------------------------------
// Probe: int64 vs int32 indices
// ---------------------------------------------------------------------------
__global__ void probe_kernel(const void* src) {
    if (blockIdx.x == 0 && threadIdx.x == 0) {
        const long long* p = (const long long*)src;
        int is64 = 1;
        for (int i = 0; i < 1024; i++) {
            long long v = p[i];
            if (v < 0 || v >= (long long)N_NODES) { is64 = 0; break; }
        }
        g_idx64 = is64;
    }
}

__device__ __forceinline__ int load_idx(const void* p, int e, int idx64) {
    return idx64 ? (int)((const long long*)p)[e] : ((const int*)p)[e];
}

// ---------------------------------------------------------------------------
// CSR build
// ---------------------------------------------------------------------------
__global__ __launch_bounds__(256) void zero_deg() {
    int i = blockIdx.x * 256 + threadIdx.x;
    if (i < N_NODES) g_deg[i] = 0;
}

__global__ __launch_bounds__(256) void count_deg(const void* dstp) {
    int e = blockIdx.x * 256 + threadIdx.x;
    if (e >= N_EDGES) return;
    int d = load_idx(dstp, e, g_idx64);
    atomicAdd(&g_deg[d], 1);
}

// scan1: per 512-node chunk, block sum -> g_part
__global__ __launch_bounds__(256) void scan1() {
    __shared__ int wsum[8];
    int t = threadIdx.x, blk = blockIdx.x;
    int i0 = blk * 512 + 2 * t, i1 = i0 + 1;
    int s = (i0 < N_NODES ? g_deg[i0] : 0) + (i1 < N_NODES ? g_deg[i1] : 0);
#pragma unroll
    for (int o = 16; o > 0; o >>= 1) s += __shfl_down_sync(0xffffffffu, s, o);
    if ((t & 31) == 0) wsum[t >> 5] = s;
    __syncthreads();
    if (t == 0) {
        int tot = 0;
#pragma unroll
        for (int w = 0; w < 8; w++) tot += wsum[w];
        g_part[blk] = tot;
    }
}

// scan2: exclusive scan of g_part (NBLK_SCAN values) in one block
__global__ __launch_bounds__(256) void scan2() {
    __shared__ int sh[256];
    int t = threadIdx.x;
    int v = (t < NBLK_SCAN) ? g_part[t] : 0;
    int orig = v;
    sh[t] = v;
    __syncthreads();
    for (int o = 1; o < 256; o <<= 1) {
        int u = (t >= o) ? sh[t - o] : 0;
        __syncthreads();
        sh[t] += u;
        __syncthreads();
    }
    if (t < NBLK_SCAN) g_partx[t] = sh[t] - orig;
}

// scan3: per-chunk exclusive scan + chunk offset -> g_off, g_cur
__global__ __launch_bounds__(256) void scan3() {
    __shared__ int wsum[8], woff[8];
    int t = threadIdx.x, blk = blockIdx.x;
    int lane = t & 31, wid = t >> 5;
    int i0 = blk * 512 + 2 * t, i1 = i0 + 1;
    int d0 = (i0 < N_NODES ? g_deg[i0] : 0);
    int d1 = (i1 < N_NODES ? g_deg[i1] : 0);
    int s = d0 + d1;
    int v = s;
#pragma unroll
    for (int o = 1; o < 32; o <<= 1) {
        int u = __shfl_up_sync(0xffffffffu, v, o);
        if (lane >= o) v += u;
    }
    if (lane == 31) wsum[wid] = v;
    __syncthreads();
    if (t < 8) {
        int p = 0;
        for (int j = 0; j < t; j++) p += wsum[j];
        woff[t] = p;
    }
    __syncthreads();
    int excl = v - s + woff[wid] + g_partx[blk];
    if (i0 < N_NODES) { g_off[i0] = excl;      g_cur[i0] = excl;      }
    if (i1 < N_NODES) { g_off[i1] = excl + d0; g_cur[i1] = excl + d0; }
}

__global__ __launch_bounds__(256) void fill_csr(const void* srcp,
                                                const void* dstp,
                                                const void* etp) {
    int e = blockIdx.x * 256 + threadIdx.x;
    if (e >= N_EDGES) return;
    int idx64 = g_idx64;
    int s  = load_idx(srcp, e, idx64);
    int d  = load_idx(dstp, e, idx64);
    int et = load_idx(etp,  e, idx64);
    int pos = atomicAdd(&g_cur[d], 1);
    g_pack[pos] = (et << 17) | s;
}

// ---------------------------------------------------------------------------
// Aggregate: one warp per dst node.
//   agg[d][b][k] = sum_{edges e into d} w_comp[et(e)][b] * x[src(e)][k]
// x (51 MB) is L2-resident; agg written streaming with st.cs.
// ---------------------------------------------------------------------------
__global__ __launch_bounds__(256) void aggregate(const float* __restrict__ x,
                                                 const float* __restrict__ w_comp) {
    __shared__ float cw[NUM_RELS * NUM_BASES];
    if (threadIdx.x < NUM_RELS * NUM_BASES)
        cw[threadIdx.x] = w_comp[threadIdx.x];
    __syncthreads();

    const int node = blockIdx.x * 8 + (threadIdx.x >> 5);
    const int lane = threadIdx.x & 31;
    if (node >= N_NODES) return;

    const int beg = g_off[node];
    const int cnt = g_deg[node];
    const float4* x4 = (const float4*)x;

    float4 acc[NUM_BASES];
#pragma unroll
    for (int b = 0; b < NUM_BASES; b++)
        acc[b] = make_float4(0.f, 0.f, 0.f, 0.f);

    for (int b0 = 0; b0 < cnt; b0 += 32) {
        int pk = (b0 + lane < cnt) ? g_pack[beg + b0 + lane] : 0;
        int m = cnt - b0;
        if (m > 32) m = 32;
#pragma unroll 2
        for (int j = 0; j < m; j++) {
            int p = __shfl_sync(0xffffffffu, pk, j);
            int src = p & 0x1FFFF;
            int et  = p >> 17;
            float4 xv = x4[(size_t)src * 32 + lane];
#pragma unroll
            for (int b = 0; b < NUM_BASES; b++) {
                float c = cw[et * NUM_BASES + b];
                acc[b].x += c * xv.x;
                acc[b].y += c * xv.y;
                acc[b].z += c * xv.z;
                acc[b].w += c * xv.w;
            }
        }
    }

    float4* ag = (float4*)g_agg + (size_t)node * NUM_BASES * 32 + lane;
#pragma unroll
    for (int b = 0; b < NUM_BASES; b++)
        __stcs(ag + b * 32, acc[b]);
}

// ---------------------------------------------------------------------------
// out[100000 x 128] = agg[100000 x 1024] @ weight[1024 x 128] + bias
// SIMT register-tile GEMM: BM=128, BN=128, BK=16, 256 thr, 8x8 micro-tile.
// As stored [k][m] (pitch 132, conflict-free), Bs row-major [k][n].
// ---------------------------------------------------------------------------
__global__ __launch_bounds__(256) void out_gemm(const float* __restrict__ W,
                                                const float* __restrict__ bias,
                                                float* __restrict__ out) {
    __shared__ float As[16][132];
    __shared__ float Bs[16][128];
    __shared__ float bs[128];

    const int tid = threadIdx.x;
    const int tx  = tid & 15;
    const int ty  = tid >> 4;
    const int m0  = blockIdx.x * 128;

    if (tid < 128) bs[tid] = bias[tid];

    float acc[8][8];
#pragma unroll
    for (int i = 0; i < 8; i++)
#pragma unroll
        for (int j = 0; j < 8; j++) acc[i][j] = 0.f;

    const int arow = tid & 127;           // 0..127 (M row)
    const int kh   = (tid >> 7) * 8;      // 0 or 8 (k half)
    const bool arow_ok = (m0 + arow) < N_NODES;
    const float* aptr = g_agg + (size_t)(m0 + arow) * KTOT + kh;

    const int brow = tid >> 5;            // 0..7
    const int bcol = (tid & 31) * 4;      // 0..124

    for (int kk = 0; kk < KTOT; kk += 16) {
        float4 a0 = make_float4(0.f, 0.f, 0.f, 0.f), a1 = a0;
        if (arow_ok) {
            a0 = *(const float4*)(aptr + kk);
            a1 = *(const float4*)(aptr + kk + 4);
        }
        As[kh + 0][arow] = a0.x; As[kh + 1][arow] = a0.y;
        As[kh + 2][arow] = a0.z; As[kh + 3][arow] = a0.w;
        As[kh + 4][arow] = a1.x; As[kh + 5][arow] = a1.y;
        As[kh + 6][arow] = a1.z; As[kh + 7][arow] = a1.w;

        *(float4*)(&Bs[brow][bcol]) =
            *(const float4*)(W + (size_t)(kk + brow) * FEAT + bcol);
        *(float4*)(&Bs[brow + 8][bcol]) =
            *(const float4*)(W + (size_t)(kk + brow + 8) * FEAT + bcol);
        __syncthreads();

#pragma unroll
        for (int k = 0; k < 16; k++) {
            float4 a0v = *(const float4*)(&As[k][ty * 8]);
            float4 a1v = *(const float4*)(&As[k][ty * 8 + 4]);
            float4 b0v = *(const float4*)(&Bs[k][tx * 8]);
            float4 b1v = *(const float4*)(&Bs[k][tx * 8 + 4]);
            float ar[8] = {a0v.x, a0v.y, a0v.z, a0v.w, a1v.x, a1v.y, a1v.z, a1v.w};
            float br[8] = {b0v.x, b0v.y, b0v.z, b0v.w, b1v.x, b1v.y, b1v.z, b1v.w};
#pragma unroll
            for (int i = 0; i < 8; i++)
#pragma unroll
                for (int j = 0; j < 8; j++)
                    acc[i][j] += ar[i] * br[j];
        }
        __syncthreads();
    }

#pragma unroll
    for (int i = 0; i < 8; i++) {
        int row = m0 + ty * 8 + i;
        if (row < N_NODES) {
            float* op = out + (size_t)row * FEAT + tx * 8;
            *(float4*)(op) = make_float4(acc[i][0] + bs[tx * 8 + 0],
                                         acc[i][1] + bs[tx * 8 + 1],
                                         acc[i][2] + bs[tx * 8 + 2],
                                         acc[i][3] + bs[tx * 8 + 3]);
            *(float4*)(op + 4) = make_float4(acc[i][4] + bs[tx * 8 + 4],
                                             acc[i][5] + bs[tx * 8 + 5],
                                             acc[i][6] + bs[tx * 8 + 6],
                                             acc[i][7] + bs[tx * 8 + 7]);
        }
    }
}

// ---------------------------------------------------------------------------
// Launch
// ---------------------------------------------------------------------------
extern "C" void kernel_launch(void* const* d_in, const int* in_sizes, int n_in,
                              void* d_out, int out_size) {
    const float* x      = (const float*)d_in[0];
    const float* weight = (const float*)d_in[1];
    const float* w_comp = (const float*)d_in[2];
    const float* h_bias = (const float*)d_in[3];
    const void*  src    = d_in[4];
    const void*  dst    = d_in[5];
    const void*  etyp   = d_in[6];
    float*       out    = (float*)d_out;

    probe_kernel<<<1, 1>>>(src);

    // CSR by destination
    zero_deg<<<(N_NODES + 255) / 256, 256>>>();
    count_deg<<<(N_EDGES + 255) / 256, 256>>>(dst);
    scan1<<<NBLK_SCAN, 256>>>();
    scan2<<<1, 256>>>();
    scan3<<<NBLK_SCAN, 256>>>();
    fill_csr<<<(N_EDGES + 255) / 256, 256>>>(src, dst, etyp);

    // Basis-weighted aggregation (no g_h, no global atomics)
    aggregate<<<(N_NODES + 7) / 8, 256>>>(x, w_comp);

    // Fused transform + bias
    out_gemm<<<(N_NODES + 127) / 128, 256>>>(weight, h_bias, out);
}

// round 6
// speedup vs baseline: 1.2961x; 1.0140x over previous
#include <cuda_runtime.h>
#include <cstdint>
#include <cstddef>

#define N_NODES  100000
#define N_EDGES  3200000
#define FEAT     128
#define NUM_RELS 16
#define NUM_BASES 8
#define KTOT     (NUM_BASES * FEAT)   // 1024

#define NBLK_SCAN 196                 // 196 * 512 = 100352 >= N_NODES

// Scratch (static device globals — no runtime allocation allowed).
__device__ float g_agg[(size_t)N_NODES * NUM_BASES * FEAT];  // 410 MB: agg[d][b][k]
__device__ int   g_deg [N_NODES];
__device__ int   g_off [N_NODES];
__device__ int   g_cur [N_NODES];
__device__ int   g_pack[N_EDGES];                            // (et<<17)|src
__device__ int   g_part [NBLK_SCAN];
__device__ int   g_partx[NBLK_SCAN];
__device__ int   g_idx64;

// ---------------------------------------------------------------------------
// f32x2 packed helpers (Blackwell base-family PTX, ok on plain sm_103)
// ---------------------------------------------------------------------------
typedef unsigned long long u64;

__device__ __forceinline__ u64 pack2(float lo, float hi) {
    u64 r;
    asm("mov.b64 %0, {%1, %2};" : "=l"(r) : "f"(lo), "f"(hi));
    return r;
}
__device__ __forceinline__ u64 dup2(float v) {
    u64 r;
    asm("mov.b64 %0, {%1, %1};" : "=l"(r) : "f"(v));
    return r;
}
__device__ __forceinline__ void fma2(u64& acc, u64 a, u64 b) {
    asm("fma.rn.f32x2 %0, %1, %2, %0;" : "+l"(acc) : "l"(a), "l"(b));
}
__device__ __forceinline__ float2 unpack2(u64 v) {
    float lo, hi;
    asm("mov.b64 {%0, %1}, %2;" : "=f"(lo), "=f"(hi) : "l"(v));
    return make_float2(lo, hi);
}

// ---------------------------------------------------------------------------
// Probe: int64 vs int32 indices
// ---------------------------------------------------------------------------
__global__ void probe_kernel(const void* src) {
    if (blockIdx.x == 0 && threadIdx.x == 0) {
        const long long* p = (const long long*)src;
        int is64 = 1;
        for (int i = 0; i < 1024; i++) {
            long long v = p[i];
            if (v < 0 || v >= (long long)N_NODES) { is64 = 0; break; }
        }
        g_idx64 = is64;
    }
}

__device__ __forceinline__ int load_idx(const void* p, int e, int idx64) {
    return idx64 ? (int)((const long long*)p)[e] : ((const int*)p)[e];
}

// ---------------------------------------------------------------------------
// CSR build
// ---------------------------------------------------------------------------
__global__ __launch_bounds__(256) void zero_deg() {
    int i = blockIdx.x * 256 + threadIdx.x;
    if (i < N_NODES) g_deg[i] = 0;
}

__global__ __launch_bounds__(256) void count_deg(const void* dstp) {
    int e = blockIdx.x * 256 + threadIdx.x;
    if (e >= N_EDGES) return;
    int d = load_idx(dstp, e, g_idx64);
    atomicAdd(&g_deg[d], 1);
}

__global__ __launch_bounds__(256) void scan1() {
    __shared__ int wsum[8];
    int t = threadIdx.x, blk = blockIdx.x;
    int i0 = blk * 512 + 2 * t, i1 = i0 + 1;
    int s = (i0 < N_NODES ? g_deg[i0] : 0) + (i1 < N_NODES ? g_deg[i1] : 0);
#pragma unroll
    for (int o = 16; o > 0; o >>= 1) s += __shfl_down_sync(0xffffffffu, s, o);
    if ((t & 31) == 0) wsum[t >> 5] = s;
    __syncthreads();
    if (t == 0) {
        int tot = 0;
#pragma unroll
        for (int w = 0; w < 8; w++) tot += wsum[w];
        g_part[blk] = tot;
    }
}

__global__ __launch_bounds__(256) void scan2() {
    __shared__ int sh[256];
    int t = threadIdx.x;
    int v = (t < NBLK_SCAN) ? g_part[t] : 0;
    int orig = v;
    sh[t] = v;
    __syncthreads();
    for (int o = 1; o < 256; o <<= 1) {
        int u = (t >= o) ? sh[t - o] : 0;
        __syncthreads();
        sh[t] += u;
        __syncthreads();
    }
    if (t < NBLK_SCAN) g_partx[t] = sh[t] - orig;
}

__global__ __launch_bounds__(256) void scan3() {
    __shared__ int wsum[8], woff[8];
    int t = threadIdx.x, blk = blockIdx.x;
    int lane = t & 31, wid = t >> 5;
    int i0 = blk * 512 + 2 * t, i1 = i0 + 1;
    int d0 = (i0 < N_NODES ? g_deg[i0] : 0);
    int d1 = (i1 < N_NODES ? g_deg[i1] : 0);
    int s = d0 + d1;
    int v = s;
#pragma unroll
    for (int o = 1; o < 32; o <<= 1) {
        int u = __shfl_up_sync(0xffffffffu, v, o);
        if (lane >= o) v += u;
    }
    if (lane == 31) wsum[wid] = v;
    __syncthreads();
    if (t < 8) {
        int p = 0;
        for (int j = 0; j < t; j++) p += wsum[j];
        woff[t] = p;
    }
    __syncthreads();
    int excl = v - s + woff[wid] + g_partx[blk];
    if (i0 < N_NODES) { g_off[i0] = excl;      g_cur[i0] = excl;      }
    if (i1 < N_NODES) { g_off[i1] = excl + d0; g_cur[i1] = excl + d0; }
}

__global__ __launch_bounds__(256) void fill_csr(const void* srcp,
                                                const void* dstp,
                                                const void* etp) {
    int e = blockIdx.x * 256 + threadIdx.x;
    if (e >= N_EDGES) return;
    int idx64 = g_idx64;
    int s  = load_idx(srcp, e, idx64);
    int d  = load_idx(dstp, e, idx64);
    int et = load_idx(etp,  e, idx64);
    int pos = atomicAdd(&g_cur[d], 1);
    g_pack[pos] = (et << 17) | s;
}

// ---------------------------------------------------------------------------
// Aggregate: one warp per dst node.
//   agg[d][b][k] = sum_{edges e into d} w_comp[et(e)][b] * x[src(e)][k]
// x (51 MB) L2-resident; agg written streaming (st.cs). f32x2 accumulate.
// ---------------------------------------------------------------------------
__global__ __launch_bounds__(256) void aggregate(const float* __restrict__ x,
                                                 const float* __restrict__ w_comp) {
    __shared__ float cw[NUM_RELS * NUM_BASES];
    if (threadIdx.x < NUM_RELS * NUM_BASES)
        cw[threadIdx.x] = w_comp[threadIdx.x];
    __syncthreads();

    const int node = blockIdx.x * 8 + (threadIdx.x >> 5);
    const int lane = threadIdx.x & 31;
    if (node >= N_NODES) return;

    const int beg = g_off[node];
    const int cnt = g_deg[node];
    const float4* x4 = (const float4*)x;

    u64 acc[NUM_BASES][2];
#pragma unroll
    for (int b = 0; b < NUM_BASES; b++) { acc[b][0] = 0ull; acc[b][1] = 0ull; }

    for (int b0 = 0; b0 < cnt; b0 += 32) {
        int pk = (b0 + lane < cnt) ? g_pack[beg + b0 + lane] : 0;
        int m = cnt - b0;
        if (m > 32) m = 32;
#pragma unroll 4
        for (int j = 0; j < m; j++) {
            int p = __shfl_sync(0xffffffffu, pk, j);
            int src = p & 0x1FFFF;
            int et  = p >> 17;
            float4 xv = x4[(size_t)src * 32 + lane];
            u64 xlo = pack2(xv.x, xv.y);
            u64 xhi = pack2(xv.z, xv.w);
#pragma unroll
            for (int b = 0; b < NUM_BASES; b++) {
                u64 c2 = dup2(cw[et * NUM_BASES + b]);
                fma2(acc[b][0], c2, xlo);
                fma2(acc[b][1], c2, xhi);
            }
        }
    }

    float4* ag = (float4*)g_agg + (size_t)node * NUM_BASES * 32 + lane;
#pragma unroll
    for (int b = 0; b < NUM_BASES; b++) {
        float2 lo = unpack2(acc[b][0]);
        float2 hi = unpack2(acc[b][1]);
        __stcs(ag + b * 32, make_float4(lo.x, lo.y, hi.x, hi.y));
    }
}

// ---------------------------------------------------------------------------
// out[100000 x 128] = agg[100000 x 1024] @ weight[1024 x 128] + bias
// BM=128, BN=128, BK=16, 256 thr, 8x8 micro-tile via fma.rn.f32x2.
// ---------------------------------------------------------------------------
__global__ __launch_bounds__(256) void out_gemm(const float* __restrict__ W,
                                                const float* __restrict__ bias,
                                                float* __restrict__ out) {
    __shared__ float As[16][132];
    __shared__ float Bs[16][128];
    __shared__ float bs[128];

    const int tid = threadIdx.x;
    const int tx  = tid & 15;
    const int ty  = tid >> 4;
    const int m0  = blockIdx.x * 128;

    if (tid < 128) bs[tid] = bias[tid];

    u64 acc[8][4];     // [i][pair j]: cols (tx*8+2j, tx*8+2j+1)
#pragma unroll
    for (int i = 0; i < 8; i++)
#pragma unroll
        for (int j = 0; j < 4; j++) acc[i][j] = 0ull;

    const int arow = tid & 127;           // M row within tile
    const int kh   = (tid >> 7) * 8;      // 0 or 8 (k half)
    const bool arow_ok = (m0 + arow) < N_NODES;
    const float* aptr = g_agg + (size_t)(m0 + arow) * KTOT + kh;

    const int brow = tid >> 5;            // 0..7
    const int bcol = (tid & 31) * 4;      // 0..124

    for (int kk = 0; kk < KTOT; kk += 16) {
        float4 a0 = make_float4(0.f, 0.f, 0.f, 0.f), a1 = a0;
        if (arow_ok) {
            a0 = *(const float4*)(aptr + kk);
            a1 = *(const float4*)(aptr + kk + 4);
        }
        As[kh + 0][arow] = a0.x; As[kh + 1][arow] = a0.y;
        As[kh + 2][arow] = a0.z; As[kh + 3][arow] = a0.w;
        As[kh + 4][arow] = a1.x; As[kh + 5][arow] = a1.y;
        As[kh + 6][arow] = a1.z; As[kh + 7][arow] = a1.w;

        *(float4*)(&Bs[brow][bcol]) =
            *(const float4*)(W + (size_t)(kk + brow) * FEAT + bcol);
        *(float4*)(&Bs[brow + 8][bcol]) =
            *(const float4*)(W + (size_t)(kk + brow + 8) * FEAT + bcol);
        __syncthreads();

#pragma unroll
        for (int k = 0; k < 16; k++) {
            float4 a0v = *(const float4*)(&As[k][ty * 8]);
            float4 a1v = *(const float4*)(&As[k][ty * 8 + 4]);
            float4 b0v = *(const float4*)(&Bs[k][tx * 8]);
            float4 b1v = *(const float4*)(&Bs[k][tx * 8 + 4]);
            u64 bd[4] = { pack2(b0v.x, b0v.y), pack2(b0v.z, b0v.w),
                          pack2(b1v.x, b1v.y), pack2(b1v.z, b1v.w) };
            float ar[8] = {a0v.x, a0v.y, a0v.z, a0v.w,
                           a1v.x, a1v.y, a1v.z, a1v.w};
#pragma unroll
            for (int i = 0; i < 8; i++) {
                u64 ad = dup2(ar[i]);
#pragma unroll
                for (int j = 0; j < 4; j++)
                    fma2(acc[i][j], ad, bd[j]);
            }
        }
        __syncthreads();
    }

#pragma unroll
    for (int i = 0; i < 8; i++) {
        int row = m0 + ty * 8 + i;
        if (row < N_NODES) {
            float* op = out + (size_t)row * FEAT + tx * 8;
            float2 p0 = unpack2(acc[i][0]);
            float2 p1 = unpack2(acc[i][1]);
            float2 p2 = unpack2(acc[i][2]);
            float2 p3 = unpack2(acc[i][3]);
            *(float4*)(op) = make_float4(p0.x + bs[tx * 8 + 0],
                                         p0.y + bs[tx * 8 + 1],
                                         p1.x + bs[tx * 8 + 2],
                                         p1.y + bs[tx * 8 + 3]);
            *(float4*)(op + 4) = make_float4(p2.x + bs[tx * 8 + 4],
                                             p2.y + bs[tx * 8 + 5],
                                             p3.x + bs[tx * 8 + 6],
                                             p3.y + bs[tx * 8 + 7]);
        }
    }
}

// ---------------------------------------------------------------------------
// Launch
// ---------------------------------------------------------------------------
extern "C" void kernel_launch(void* const* d_in, const int* in_sizes, int n_in,
                              void* d_out, int out_size) {
    const float* x      = (const float*)d_in[0];
    const float* weight = (const float*)d_in[1];
    const float* w_comp = (const float*)d_in[2];
    const float* h_bias = (const float*)d_in[3];
    const void*  src    = d_in[4];
    const void*  dst    = d_in[5];
    const void*  etyp   = d_in[6];
    float*       out    = (float*)d_out;

    probe_kernel<<<1, 1>>>(src);

    // CSR by destination
    zero_deg<<<(N_NODES + 255) / 256, 256>>>();
    count_deg<<<(N_EDGES + 255) / 256, 256>>>(dst);
    scan1<<<NBLK_SCAN, 256>>>();
    scan2<<<1, 256>>>();
    scan3<<<NBLK_SCAN, 256>>>();
    fill_csr<<<(N_EDGES + 255) / 256, 256>>>(src, dst, etyp);

    // Basis-weighted aggregation (no global atomics)
    aggregate<<<(N_NODES + 7) / 8, 256>>>(x, w_comp);

    // Fused transform + bias
    out_gemm<<<(N_NODES + 127) / 128, 256>>>(weight, h_bias, out);
}

// round 10
// speedup vs baseline: 2.1540x; 1.6619x over previous
#include <cuda_runtime.h>
#include <cstdint>
#include <cstddef>

#define N_NODES  100000
#define N_EDGES  3200000
#define FEAT     128
#define NUM_RELS 16
#define NUM_BASES 8
#define KTOT     (NUM_BASES * FEAT)   // 1024

#define NBLK_SCAN 196                 // 196 * 512 = 100352 >= N_NODES

// Scratch (static device globals — no runtime allocation allowed).
__device__ float g_agg[(size_t)N_NODES * NUM_BASES * FEAT];  // 410 MB, tf32-rounded
__device__ float g_bt [(size_t)FEAT * KTOT];                 // 512 KB: Bt[n][k], tf32
__device__ int   g_deg [N_NODES];
__device__ int   g_off [N_NODES];
__device__ int   g_cur [N_NODES];
__device__ int   g_pack[N_EDGES];                            // (et<<17)|src
__device__ int   g_part [NBLK_SCAN];
__device__ int   g_partx[NBLK_SCAN];
__device__ int   g_idx64;

// ---------------------------------------------------------------------------
// Helpers
// ---------------------------------------------------------------------------
typedef unsigned long long u64;

__device__ __forceinline__ u64 pack2(float lo, float hi) {
    u64 r; asm("mov.b64 %0, {%1, %2};" : "=l"(r) : "f"(lo), "f"(hi)); return r;
}
__device__ __forceinline__ u64 dup2(float v) {
    u64 r; asm("mov.b64 %0, {%1, %1};" : "=l"(r) : "f"(v)); return r;
}
__device__ __forceinline__ void fma2(u64& acc, u64 a, u64 b) {
    asm("fma.rn.f32x2 %0, %1, %2, %0;" : "+l"(acc) : "l"(a), "l"(b));
}
__device__ __forceinline__ float2 unpack2(u64 v) {
    float lo, hi; asm("mov.b64 {%0, %1}, %2;" : "=f"(lo), "=f"(hi) : "l"(v));
    return make_float2(lo, hi);
}
__device__ __forceinline__ float f2tf32f(float f) {
    uint32_t r; asm("cvt.rna.tf32.f32 %0, %1;" : "=r"(r) : "f"(f));
    return __uint_as_float(r);
}
__device__ __forceinline__ void mma_tf32(float* c,
                                         uint32_t a0, uint32_t a1, uint32_t a2, uint32_t a3,
                                         uint32_t b0, uint32_t b1) {
    asm volatile("mma.sync.aligned.m16n8k8.row.col.f32.tf32.tf32.f32 "
                 "{%0,%1,%2,%3}, {%4,%5,%6,%7}, {%8,%9}, {%0,%1,%2,%3};"
                 : "+f"(c[0]), "+f"(c[1]), "+f"(c[2]), "+f"(c[3])
                 : "r"(a0), "r"(a1), "r"(a2), "r"(a3), "r"(b0), "r"(b1));
}

// ---------------------------------------------------------------------------
// Probe: int64 vs int32 indices (parallel: 1024 loads, 1 block)
// ---------------------------------------------------------------------------
__global__ void probe_kernel(const void* src) {
    __shared__ int bad;
    if (threadIdx.x == 0) bad = 0;
    __syncthreads();
    long long v = ((const long long*)src)[threadIdx.x];
    if (v < 0 || v >= (long long)N_NODES) bad = 1;
    __syncthreads();
    if (threadIdx.x == 0) g_idx64 = bad ? 0 : 1;
}

__device__ __forceinline__ int load_idx(const void* p, int e, int idx64) {
    return idx64 ? (int)((const long long*)p)[e] : ((const int*)p)[e];
}

// ---------------------------------------------------------------------------
// Bt[n][k] = tf32(weight[k/128][k%128][n])   (transposed B for out_gemm)
// ---------------------------------------------------------------------------
__global__ __launch_bounds__(256) void prep_bt(const float* __restrict__ weight) {
    int idx = blockIdx.x * 256 + threadIdx.x;       // 128*1024 = 131072
    if (idx >= FEAT * KTOT) return;
    int n = idx >> 10, k = idx & 1023;
    int b = k >> 7, kin = k & 127;
    g_bt[idx] = f2tf32f(weight[((size_t)b * FEAT + kin) * FEAT + n]);
}

// ---------------------------------------------------------------------------
// CSR build
// ---------------------------------------------------------------------------
__global__ __launch_bounds__(256) void zero_deg() {
    int i = blockIdx.x * 256 + threadIdx.x;
    if (i < N_NODES) g_deg[i] = 0;
}

__global__ __launch_bounds__(256) void count_deg(const void* dstp) {
    int e = blockIdx.x * 256 + threadIdx.x;
    if (e >= N_EDGES) return;
    int d = load_idx(dstp, e, g_idx64);
    atomicAdd(&g_deg[d], 1);
}

__global__ __launch_bounds__(256) void scan1() {
    __shared__ int wsum[8];
    int t = threadIdx.x, blk = blockIdx.x;
    int i0 = blk * 512 + 2 * t, i1 = i0 + 1;
    int s = (i0 < N_NODES ? g_deg[i0] : 0) + (i1 < N_NODES ? g_deg[i1] : 0);
#pragma unroll
    for (int o = 16; o > 0; o >>= 1) s += __shfl_down_sync(0xffffffffu, s, o);
    if ((t & 31) == 0) wsum[t >> 5] = s;
    __syncthreads();
    if (t == 0) {
        int tot = 0;
#pragma unroll
        for (int w = 0; w < 8; w++) tot += wsum[w];
        g_part[blk] = tot;
    }
}

__global__ __launch_bounds__(256) void scan2() {
    __shared__ int sh[256];
    int t = threadIdx.x;
    int v = (t < NBLK_SCAN) ? g_part[t] : 0;
    int orig = v;
    sh[t] = v;
    __syncthreads();
    for (int o = 1; o < 256; o <<= 1) {
        int u = (t >= o) ? sh[t - o] : 0;
        __syncthreads();
        sh[t] += u;
        __syncthreads();
    }
    if (t < NBLK_SCAN) g_partx[t] = sh[t] - orig;
}

__global__ __launch_bounds__(256) void scan3() {
    __shared__ int wsum[8], woff[8];
    int t = threadIdx.x, blk = blockIdx.x;
    int lane = t & 31, wid = t >> 5;
    int i0 = blk * 512 + 2 * t, i1 = i0 + 1;
    int d0 = (i0 < N_NODES ? g_deg[i0] : 0);
    int d1 = (i1 < N_NODES ? g_deg[i1] : 0);
    int s = d0 + d1;
    int v = s;
#pragma unroll
    for (int o = 1; o < 32; o <<= 1) {
        int u = __shfl_up_sync(0xffffffffu, v, o);
        if (lane >= o) v += u;
    }
    if (lane == 31) wsum[wid] = v;
    __syncthreads();
    if (t < 8) {
        int p = 0;
        for (int j = 0; j < t; j++) p += wsum[j];
        woff[t] = p;
    }
    __syncthreads();
    int excl = v - s + woff[wid] + g_partx[blk];
    if (i0 < N_NODES) { g_off[i0] = excl;      g_cur[i0] = excl;      }
    if (i1 < N_NODES) { g_off[i1] = excl + d0; g_cur[i1] = excl + d0; }
}

__global__ __launch_bounds__(256) void fill_csr(const void* srcp,
                                                const void* dstp,
                                                const void* etp) {
    int e = blockIdx.x * 256 + threadIdx.x;
    if (e >= N_EDGES) return;
    int idx64 = g_idx64;
    int s  = load_idx(srcp, e, idx64);
    int d  = load_idx(dstp, e, idx64);
    int et = load_idx(etp,  e, idx64);
    int pos = atomicAdd(&g_cur[d], 1);
    g_pack[pos] = (et << 17) | s;
}

// ---------------------------------------------------------------------------
// Aggregate: one warp per dst node; f32x2 accumulate; tf32-round on store.
// ---------------------------------------------------------------------------
__global__ __launch_bounds__(256) void aggregate(const float* __restrict__ x,
                                                 const float* __restrict__ w_comp) {
    __shared__ float cw[NUM_RELS * NUM_BASES];
    if (threadIdx.x < NUM_RELS * NUM_BASES)
        cw[threadIdx.x] = w_comp[threadIdx.x];
    __syncthreads();

    const int node = blockIdx.x * 8 + (threadIdx.x >> 5);
    const int lane = threadIdx.x & 31;
    if (node >= N_NODES) return;

    const int beg = g_off[node];
    const int cnt = g_deg[node];
    const float4* x4 = (const float4*)x;

    u64 acc[NUM_BASES][2];
#pragma unroll
    for (int b = 0; b < NUM_BASES; b++) { acc[b][0] = 0ull; acc[b][1] = 0ull; }

    for (int b0 = 0; b0 < cnt; b0 += 32) {
        int pk = (b0 + lane < cnt) ? g_pack[beg + b0 + lane] : 0;
        int m = cnt - b0;
        if (m > 32) m = 32;
#pragma unroll 4
        for (int j = 0; j < m; j++) {
            int p = __shfl_sync(0xffffffffu, pk, j);
            int src = p & 0x1FFFF;
            int et  = p >> 17;
            float4 xv = x4[(size_t)src * 32 + lane];
            u64 xlo = pack2(xv.x, xv.y);
            u64 xhi = pack2(xv.z, xv.w);
#pragma unroll
            for (int b = 0; b < NUM_BASES; b++) {
                u64 c2 = dup2(cw[et * NUM_BASES + b]);
                fma2(acc[b][0], c2, xlo);
                fma2(acc[b][1], c2, xhi);
            }
        }
    }

    float4* ag = (float4*)g_agg + (size_t)node * NUM_BASES * 32 + lane;
#pragma unroll
    for (int b = 0; b < NUM_BASES; b++) {
        float2 lo = unpack2(acc[b][0]);
        float2 hi = unpack2(acc[b][1]);
        __stcs(ag + b * 32, make_float4(f2tf32f(lo.x), f2tf32f(lo.y),
                                        f2tf32f(hi.x), f2tf32f(hi.y)));
    }
}

// ---------------------------------------------------------------------------
// out[100000 x 128] = agg[100000 x 1024] @ Bt^T + bias  via tf32 mma.sync.
// BM=128, BN=128, BK=32; 256 thr = 8 warps (4M x 2N); warp tile 32x64.
// As/Bs: [row][k] pitch 36 floats -> conflict-free fragment LDS.
// ---------------------------------------------------------------------------
#define GP 36
__global__ __launch_bounds__(256, 2) void out_gemm(const float* __restrict__ bias,
                                                   float* __restrict__ out) {
    __shared__ float As[128 * GP];
    __shared__ float Bs[128 * GP];
    __shared__ float bsm[128];

    const int tid    = threadIdx.x;
    const int wid    = tid >> 5;
    const int lane   = tid & 31;
    const int warp_m = wid & 3;
    const int warp_n = wid >> 2;
    const int grp    = lane >> 2;
    const int tig    = lane & 3;
    const int m0     = blockIdx.x * 128;

    if (tid < 128) bsm[tid] = bias[tid];

    float acc[2][8][4];
#pragma unroll
    for (int i = 0; i < 2; i++)
#pragma unroll
        for (int j = 0; j < 8; j++)
#pragma unroll
            for (int q = 0; q < 4; q++) acc[i][j][q] = 0.f;

    const int lrow = tid >> 1;             // 0..127 (A m-row / B n-row)
    const int lkq  = (tid & 1) * 16;       // k sub-chunk 0 or 16
    const bool aok = (m0 + lrow) < N_NODES;
    const float* aptr = g_agg + (size_t)(m0 + lrow) * KTOT + lkq;
    const float* bptr = g_bt  + (size_t)lrow * KTOT + lkq;
    float* asm_p = As + lrow * GP + lkq;
    float* bsm_p = Bs + lrow * GP + lkq;

    for (int kk = 0; kk < KTOT; kk += 32) {
        __syncthreads();                    // prior compute done
#pragma unroll
        for (int q = 0; q < 4; q++) {
            float4 av = make_float4(0.f, 0.f, 0.f, 0.f);
            if (aok) av = *(const float4*)(aptr + kk + q * 4);
            float4 bv = *(const float4*)(bptr + kk + q * 4);
            *(float4*)(asm_p + q * 4) = av;
            *(float4*)(bsm_p + q * 4) = bv;
        }
        __syncthreads();

#pragma unroll
        for (int ks = 0; ks < 4; ks++) {
            const int k0 = ks * 8;
            uint32_t bf[8][2];
#pragma unroll
            for (int j = 0; j < 8; j++) {
                const float* bp = Bs + (warp_n * 64 + j * 8 + grp) * GP + k0 + tig;
                bf[j][0] = __float_as_uint(bp[0]);
                bf[j][1] = __float_as_uint(bp[4]);
            }
#pragma unroll
            for (int i = 0; i < 2; i++) {
                const float* ap = As + (warp_m * 32 + i * 16 + grp) * GP + k0 + tig;
                uint32_t a0 = __float_as_uint(ap[0]);
                uint32_t a1 = __float_as_uint(ap[8 * GP]);
                uint32_t a2 = __float_as_uint(ap[4]);
                uint32_t a3 = __float_as_uint(ap[8 * GP + 4]);
#pragma unroll
                for (int j = 0; j < 8; j++)
                    mma_tf32(acc[i][j], a0, a1, a2, a3, bf[j][0], bf[j][1]);
            }
        }
    }

#pragma unroll
    for (int i = 0; i < 2; i++) {
        int row_lo = m0 + warp_m * 32 + i * 16 + grp;
        int row_hi = row_lo + 8;
#pragma unroll
        for (int j = 0; j < 8; j++) {
            int col = warp_n * 64 + j * 8 + 2 * tig;
            if (row_lo < N_NODES)
                *(float2*)(out + (size_t)row_lo * FEAT + col) =
                    make_float2(acc[i][j][0] + bsm[col],
                                acc[i][j][1] + bsm[col + 1]);
            if (row_hi < N_NODES)
                *(float2*)(out + (size_t)row_hi * FEAT + col) =
                    make_float2(acc[i][j][2] + bsm[col],
                                acc[i][j][3] + bsm[col + 1]);
        }
    }
}

// ---------------------------------------------------------------------------
// Launch
// ---------------------------------------------------------------------------
extern "C" void kernel_launch(void* const* d_in, const int* in_sizes, int n_in,
                              void* d_out, int out_size) {
    const float* x      = (const float*)d_in[0];
    const float* weight = (const float*)d_in[1];
    const float* w_comp = (const float*)d_in[2];
    const float* h_bias = (const float*)d_in[3];
    const void*  src    = d_in[4];
    const void*  dst    = d_in[5];
    const void*  etyp   = d_in[6];
    float*       out    = (float*)d_out;

    probe_kernel<<<1, 1024>>>(src);
    prep_bt<<<(FEAT * KTOT + 255) / 256, 256>>>(weight);

    // CSR by destination
    zero_deg<<<(N_NODES + 255) / 256, 256>>>();
    count_deg<<<(N_EDGES + 255) / 256, 256>>>(dst);
    scan1<<<NBLK_SCAN, 256>>>();
    scan2<<<1, 256>>>();
    scan3<<<NBLK_SCAN, 256>>>();
    fill_csr<<<(N_EDGES + 255) / 256, 256>>>(src, dst, etyp);

    // Basis-weighted aggregation (tf32-rounded output)
    aggregate<<<(N_NODES + 7) / 8, 256>>>(x, w_comp);

    // Fused transform + bias (tf32 tensor-core GEMM)
    out_gemm<<<(N_NODES + 127) / 128, 256>>>(h_bias, out);
}